// round 9
// baseline (speedup 1.0000x reference)
#include <cuda_runtime.h>
#include <cstdint>

// Shapes (fixed by the problem)
#define S_IN   2048
#define S_T    2048
#define BATCH  8
#define HID    64

#define TM     16            // t-rows per CTA
#define SC     256           // s-chunk size
#define NCHUNK (S_IN / SC)   // 8
#define BPITCH 264           // sBT pitch (floats), 256 + 8 pad
#define LPITCH 68            // staging pitch for sWT (linear stage)
#define THREADS 512

// SMEM layout (floats):
//   sS  [TM][2048]       scores            32768
//   sBT [64][BPITCH]     input^T chunk     16896
//   sAT [64][16]         lin out (h-major)  1024
#define SS_FLOATS  (TM * S_IN)
#define BT_FLOATS  (HID * BPITCH)
#define AT_FLOATS  (HID * 16)
#define SMEM_FLOATS (SS_FLOATS + BT_FLOATS + AT_FLOATS)

typedef unsigned long long ull;

__device__ __forceinline__ ull pack_dup(float x) {
    ull r; asm("mov.b64 %0, {%1, %2};" : "=l"(r) : "f"(x), "f"(x)); return r;
}
__device__ __forceinline__ void unpack2(ull v, float& lo, float& hi) {
    asm("mov.b64 {%0, %1}, %2;" : "=f"(lo), "=f"(hi) : "l"(v));
}
__device__ __forceinline__ void fma2(ull& acc, ull a, ull b) {
    asm("fma.rn.f32x2 %0, %1, %2, %0;" : "+l"(acc) : "l"(a), "l"(b));
}

__device__ __forceinline__ float warp_sum(float v) {
    v += __shfl_xor_sync(0xffffffffu, v, 16);
    v += __shfl_xor_sync(0xffffffffu, v, 8);
    v += __shfl_xor_sync(0xffffffffu, v, 4);
    v += __shfl_xor_sync(0xffffffffu, v, 2);
    v += __shfl_xor_sync(0xffffffffu, v, 1);
    return v;
}
__device__ __forceinline__ float warp_max(float v) {
    v = fmaxf(v, __shfl_xor_sync(0xffffffffu, v, 16));
    v = fmaxf(v, __shfl_xor_sync(0xffffffffu, v, 8));
    v = fmaxf(v, __shfl_xor_sync(0xffffffffu, v, 4));
    v = fmaxf(v, __shfl_xor_sync(0xffffffffu, v, 2));
    v = fmaxf(v, __shfl_xor_sync(0xffffffffu, v, 1));
    return v;
}

__global__ void __launch_bounds__(THREADS, 1)
attn_fused_kernel(const float* __restrict__ inp,        // (S_IN, B, H)
                  const float* __restrict__ tgt,        // (S_T, B, H)
                  const unsigned char* __restrict__ msk,// (B, S_T, S_IN) bool
                  const float* __restrict__ Wm,         // (H, H)  W[o][h]
                  const float* __restrict__ bias,       // (H)
                  float* __restrict__ out)              // (B, S_T, S_IN)
{
    extern __shared__ float sm[];
    float* sS  = sm;                        // TM * 2048
    float* sBT = sm + SS_FLOATS;            // [h][s] transposed input chunk
    float* sAT = sBT + BT_FLOATS;           // [h][r] linear output, transposed

    const int tid = threadIdx.x;
    const int b   = blockIdx.x >> 7;          // 8 batches
    const int t0  = (blockIdx.x & 127) << 4;  // tile of 16 t-rows

    // thread -> (s-row, h-half) for chunk staging; warp lanes share one half
    const int srow = tid & 255;     // s index within chunk
    const int half = tid >> 8;      // 0: h 0..31, 1: h 32..63

    // ---------------- prefetch chunk 0 into registers ----------------
    float4 pf[8];
    {
        const float4* src = reinterpret_cast<const float4*>(
            inp + ((size_t)(srow * BATCH + b)) * HID + half * 32);
        #pragma unroll
        for (int i = 0; i < 8; ++i) pf[i] = src[i];
    }

    // ---------------- stage W (transposed) + target tile in sS region ----------------
    float* sWT = sS;                  // 64 * LPITCH floats
    float* sTg = sS + HID * LPITCH;   // TM * 64 floats
    if (tid < 256) {
        const int o  = tid >> 2;
        const int hq = (tid & 3) * 16;
        #pragma unroll
        for (int k = 0; k < 4; ++k) {
            float4 wv = *reinterpret_cast<const float4*>(Wm + o * HID + hq + 4 * k);
            sWT[(hq + 4 * k + 0) * LPITCH + o] = wv.x;
            sWT[(hq + 4 * k + 1) * LPITCH + o] = wv.y;
            sWT[(hq + 4 * k + 2) * LPITCH + o] = wv.z;
            sWT[(hq + 4 * k + 3) * LPITCH + o] = wv.w;
        }
        const int r  = tid >> 4;
        const int hh = (tid & 15) * 4;
        *reinterpret_cast<float4*>(sTg + r * HID + hh) =
            *reinterpret_cast<const float4*>(tgt + ((size_t)((t0 + r) * BATCH + b)) * HID + hh);
    }
    __syncthreads();

    // ---------------- sAT[o][r] = (target_tile @ W^T + bias)[r][o] ----------------
    if (tid < 256) {
        const int r  = tid >> 4;
        const int o0 = (tid & 15) * 4;
        float4 acc = *reinterpret_cast<const float4*>(bias + o0);
        #pragma unroll
        for (int h = 0; h < HID; ++h) {
            const float  tv = sTg[r * HID + h];
            const float4 wv = *reinterpret_cast<const float4*>(sWT + h * LPITCH + o0);
            acc.x += tv * wv.x;
            acc.y += tv * wv.y;
            acc.z += tv * wv.z;
            acc.w += tv * wv.w;
        }
        sAT[(o0 + 0) * 16 + r] = acc.x;
        sAT[(o0 + 1) * 16 + r] = acc.y;
        sAT[(o0 + 2) * 16 + r] = acc.z;
        sAT[(o0 + 3) * 16 + r] = acc.w;
    }
    // (loop-top __syncthreads() makes sAT visible before first use)

    const int wid  = tid >> 5;
    const int lane = tid & 31;
    const int rg   = wid >> 3;                  // row group: rows rg*8 .. rg*8+7
    const int col  = (wid & 7) * 32 + lane;     // s-col within chunk (0..255)

    // ---------------- main loop over s-chunks ----------------
    for (int c = 0; c < NCHUNK; ++c) {
        __syncthreads();   // prev compute done reading sBT; sAT visible (c==0)
        // transpose-store prefetched chunk into sBT[h][s] (lanes: consecutive s, same h)
        #pragma unroll
        for (int i = 0; i < 8; ++i) {
            const int h0 = half * 32 + 4 * i;
            sBT[(h0 + 0) * BPITCH + srow] = pf[i].x;
            sBT[(h0 + 1) * BPITCH + srow] = pf[i].y;
            sBT[(h0 + 2) * BPITCH + srow] = pf[i].z;
            sBT[(h0 + 3) * BPITCH + srow] = pf[i].w;
        }
        __syncthreads();
        // prefetch next chunk (latency hidden by compute below)
        if (c + 1 < NCHUNK) {
            const float4* src = reinterpret_cast<const float4*>(
                inp + ((size_t)(((c + 1) * SC + srow) * BATCH + b)) * HID + half * 32);
            #pragma unroll
            for (int i = 0; i < 8; ++i) pf[i] = src[i];
        }

        // 8 rows x 1 col per lane; rows paired into f32x2 accumulators
        ull acc0 = 0ull, acc1 = 0ull, acc2 = 0ull, acc3 = 0ull;
        const float* aBase = sAT + rg * 8;
        const float* bCol  = sBT + col;
        #pragma unroll
        for (int h = 0; h < HID; ++h) {
            const ulonglong2 aP = *reinterpret_cast<const ulonglong2*>(aBase + h * 16);     // rows +0..3
            const ulonglong2 aQ = *reinterpret_cast<const ulonglong2*>(aBase + h * 16 + 4); // rows +4..7
            const ull bb = pack_dup(bCol[h * BPITCH]);
            fma2(acc0, aP.x, bb);
            fma2(acc1, aP.y, bb);
            fma2(acc2, aQ.x, bb);
            fma2(acc3, aQ.y, bb);
        }
        // store scores (consecutive lanes -> consecutive cols, conflict-free)
        float* dst = sS + c * SC + col;
        float lo, hi;
        unpack2(acc0, lo, hi);
        dst[(rg * 8 + 0) * S_IN] = lo;  dst[(rg * 8 + 1) * S_IN] = hi;
        unpack2(acc1, lo, hi);
        dst[(rg * 8 + 2) * S_IN] = lo;  dst[(rg * 8 + 3) * S_IN] = hi;
        unpack2(acc2, lo, hi);
        dst[(rg * 8 + 4) * S_IN] = lo;  dst[(rg * 8 + 5) * S_IN] = hi;
        unpack2(acc3, lo, hi);
        dst[(rg * 8 + 6) * S_IN] = lo;  dst[(rg * 8 + 7) * S_IN] = hi;
    }
    __syncthreads();

    // ---------------- register-resident epilogue: one warp per row ----------------
    // mean -> abs/mask -> max -> exp -> normalize, single SMEM read pass
    {
        const float NEG_INF = __int_as_float(0xff800000);
        const int r = wid;                           // 16 warps, 16 rows
        const float* row = sS + r * S_IN;
        const size_t gbase = ((size_t)(b * S_T + (t0 + r))) * S_IN;

        // load full row into registers (64 regs) + sum
        float4 v[16];
        float s = 0.f;
        #pragma unroll
        for (int i = 0; i < 16; ++i) {
            v[i] = *reinterpret_cast<const float4*>(row + i * 128 + lane * 4);
            s += (v[i].x + v[i].y) + (v[i].z + v[i].w);
        }
        s = warp_sum(s);
        const float mean = s * (1.0f / 2048.0f);

        // y = |x - mean|, apply mask (-inf), track max (all in registers)
        float m = NEG_INF;
        #pragma unroll
        for (int i = 0; i < 16; ++i) {
            const unsigned int mk = *reinterpret_cast<const unsigned int*>(
                msk + gbase + i * 128 + lane * 4);
            v[i].x = fabsf(v[i].x - mean);
            v[i].y = fabsf(v[i].y - mean);
            v[i].z = fabsf(v[i].z - mean);
            v[i].w = fabsf(v[i].w - mean);
            if (mk & 0x000000FFu) v[i].x = NEG_INF;
            if (mk & 0x0000FF00u) v[i].y = NEG_INF;
            if (mk & 0x00FF0000u) v[i].z = NEG_INF;
            if (mk & 0xFF000000u) v[i].w = NEG_INF;
            m = fmaxf(m, fmaxf(fmaxf(v[i].x, v[i].y), fmaxf(v[i].z, v[i].w)));
        }
        m = warp_max(m);

        // e = exp(y - max); sum
        float l = 0.f;
        #pragma unroll
        for (int i = 0; i < 16; ++i) {
            v[i].x = __expf(v[i].x - m);
            v[i].y = __expf(v[i].y - m);
            v[i].z = __expf(v[i].z - m);
            v[i].w = __expf(v[i].w - m);
            l += (v[i].x + v[i].y) + (v[i].z + v[i].w);
        }
        l = warp_sum(l);
        const float inv = 1.0f / l;

        // write normalized probabilities straight to GMEM
        #pragma unroll
        for (int i = 0; i < 16; ++i) {
            v[i].x *= inv; v[i].y *= inv; v[i].z *= inv; v[i].w *= inv;
            *reinterpret_cast<float4*>(out + gbase + i * 128 + lane * 4) = v[i];
        }
    }
}

extern "C" void kernel_launch(void* const* d_in, const int* in_sizes, int n_in,
                              void* d_out, int out_size)
{
    const float*         inp  = (const float*)d_in[0];
    const float*         tgt  = (const float*)d_in[1];
    const unsigned char* msk  = (const unsigned char*)d_in[2];
    const float*         Wm   = (const float*)d_in[3];
    const float*         bias = (const float*)d_in[4];
    float*               out  = (float*)d_out;

    const int smem_bytes = SMEM_FLOATS * (int)sizeof(float); // 202752 B
    cudaFuncSetAttribute(attn_fused_kernel,
                         cudaFuncAttributeMaxDynamicSharedMemorySize, smem_bytes);

    dim3 grid(BATCH * (S_T / TM));  // 1024 CTAs
    dim3 block(THREADS);
    attn_fused_kernel<<<grid, block, smem_bytes>>>(inp, tgt, msk, Wm, bias, out);
}

// round 10
// speedup vs baseline: 1.0397x; 1.0397x over previous
#include <cuda_runtime.h>
#include <cstdint>

// Shapes (fixed by the problem)
#define S_IN   2048
#define S_T    2048
#define BATCH  8
#define HID    64

#define TM     16            // t-rows per CTA
#define SC     256           // s-chunk size
#define NCHUNK (S_IN / SC)   // 8
#define BPITCH 264           // sBT pitch (floats)
#define SSP    2052          // sS pitch (floats): 2048+4 -> conflict-free score STS.64
#define LPITCH 68            // staging pitch for sWT (linear stage)
#define THREADS 128

// SMEM layout (floats):
//   sS  [TM][SSP]        scores            32832
//   sBT [64][BPITCH]     input^T chunk     16896
//   sAT [64][16]         lin out (h-major)  1024
#define SS_FLOATS  (TM * SSP)
#define BT_FLOATS  (HID * BPITCH)
#define AT_FLOATS  (HID * 16)
#define SMEM_FLOATS (SS_FLOATS + BT_FLOATS + AT_FLOATS)

typedef unsigned long long ull;

__device__ __forceinline__ ull pack_dup(float x) {
    ull r; asm("mov.b64 %0, {%1, %2};" : "=l"(r) : "f"(x), "f"(x)); return r;
}
__device__ __forceinline__ void fma2(ull& acc, ull a, ull b) {
    asm("fma.rn.f32x2 %0, %1, %2, %0;" : "+l"(acc) : "l"(a), "l"(b));
}

__device__ __forceinline__ float warp_sum(float v) {
    v += __shfl_xor_sync(0xffffffffu, v, 16);
    v += __shfl_xor_sync(0xffffffffu, v, 8);
    v += __shfl_xor_sync(0xffffffffu, v, 4);
    v += __shfl_xor_sync(0xffffffffu, v, 2);
    v += __shfl_xor_sync(0xffffffffu, v, 1);
    return v;
}
__device__ __forceinline__ float warp_max(float v) {
    v = fmaxf(v, __shfl_xor_sync(0xffffffffu, v, 16));
    v = fmaxf(v, __shfl_xor_sync(0xffffffffu, v, 8));
    v = fmaxf(v, __shfl_xor_sync(0xffffffffu, v, 4));
    v = fmaxf(v, __shfl_xor_sync(0xffffffffu, v, 2));
    v = fmaxf(v, __shfl_xor_sync(0xffffffffu, v, 1));
    return v;
}

__global__ void __launch_bounds__(THREADS, 1)
attn_fused_kernel(const float* __restrict__ inp,        // (S_IN, B, H)
                  const float* __restrict__ tgt,        // (S_T, B, H)
                  const unsigned char* __restrict__ msk,// (B, S_T, S_IN) bool
                  const float* __restrict__ Wm,         // (H, H)  W[o][h]
                  const float* __restrict__ bias,       // (H)
                  float* __restrict__ out)              // (B, S_T, S_IN)
{
    extern __shared__ float sm[];
    float* sS  = sm;                        // TM rows, pitch SSP
    float* sBT = sm + SS_FLOATS;            // [h][s] transposed input chunk
    float* sAT = sBT + BT_FLOATS;           // [h][r] linear output, transposed

    const int tid = threadIdx.x;
    const int b   = blockIdx.x >> 7;          // 8 batches
    const int t0  = (blockIdx.x & 127) << 4;  // tile of 16 t-rows

    // ---------------- prefetch chunk 0, rows 0..127 (one full s-row/thread) ----
    float4 pf[16];
    {
        const float4* src = reinterpret_cast<const float4*>(
            inp + ((size_t)(tid * BATCH + b)) * HID);
        #pragma unroll
        for (int i = 0; i < 16; ++i) pf[i] = src[i];
    }

    // ---------------- stage W (transposed) + target tile in sS region ----------
    float* sWT = sS;                  // 64 * LPITCH floats
    float* sTg = sS + HID * LPITCH;   // TM * 64 floats
    #pragma unroll
    for (int vb = 0; vb < 2; ++vb) {
        const int vtid = tid + vb * 128;
        const int o  = vtid >> 2;
        const int hq = (vtid & 3) * 16;
        #pragma unroll
        for (int k = 0; k < 4; ++k) {
            float4 wv = *reinterpret_cast<const float4*>(Wm + o * HID + hq + 4 * k);
            sWT[(hq + 4 * k + 0) * LPITCH + o] = wv.x;
            sWT[(hq + 4 * k + 1) * LPITCH + o] = wv.y;
            sWT[(hq + 4 * k + 2) * LPITCH + o] = wv.z;
            sWT[(hq + 4 * k + 3) * LPITCH + o] = wv.w;
        }
        const int r  = vtid >> 4;
        const int hh = (vtid & 15) * 4;
        *reinterpret_cast<float4*>(sTg + r * HID + hh) =
            *reinterpret_cast<const float4*>(tgt + ((size_t)((t0 + r) * BATCH + b)) * HID + hh);
    }
    __syncthreads();

    // ---------------- sAT[o][r] = (target_tile @ W^T + bias)[r][o] -------------
    #pragma unroll
    for (int vb = 0; vb < 2; ++vb) {
        const int vtid = tid + vb * 128;
        const int r  = vtid >> 4;
        const int o0 = (vtid & 15) * 4;
        float4 acc = *reinterpret_cast<const float4*>(bias + o0);
        #pragma unroll
        for (int h = 0; h < HID; ++h) {
            const float  tv = sTg[r * HID + h];
            const float4 wv = *reinterpret_cast<const float4*>(sWT + h * LPITCH + o0);
            acc.x += tv * wv.x;
            acc.y += tv * wv.y;
            acc.z += tv * wv.z;
            acc.w += tv * wv.w;
        }
        sAT[(o0 + 0) * 16 + r] = acc.x;
        sAT[(o0 + 1) * 16 + r] = acc.y;
        sAT[(o0 + 2) * 16 + r] = acc.z;
        sAT[(o0 + 3) * 16 + r] = acc.w;
    }

    // GEMM lane mapping: warp covers all 16 rows x 64 cols [wid*64, wid*64+64)
    // lane = (rg, cg): rows rg*4..rg*4+3, cols wid*64 + 2*cg + 16*j + {0,1}, j=0..3
    const int wid  = tid >> 5;
    const int lane = tid & 31;
    const int rg   = lane >> 3;                 // 0..3
    const int cg   = lane & 7;                  // 0..7
    const int colbase = wid * 64 + 2 * cg;

    // ---------------- main loop over s-chunks ----------------
    for (int c = 0; c < NCHUNK; ++c) {
        __syncthreads();   // prev GEMM done reading sBT; sAT visible (c==0)

        // stage half 0 (rows 0..127 of chunk): transpose pf -> sBT[h][s]
        #pragma unroll
        for (int i = 0; i < 16; ++i) {
            sBT[(4 * i + 0) * BPITCH + tid] = pf[i].x;
            sBT[(4 * i + 1) * BPITCH + tid] = pf[i].y;
            sBT[(4 * i + 2) * BPITCH + tid] = pf[i].z;
            sBT[(4 * i + 3) * BPITCH + tid] = pf[i].w;
        }
        // load + stage half 1 (rows 128..255) — latency exposed once per chunk
        {
            const float4* src = reinterpret_cast<const float4*>(
                inp + ((size_t)((c * SC + 128 + tid) * BATCH + b)) * HID);
            #pragma unroll
            for (int i = 0; i < 16; ++i) pf[i] = src[i];
            const int srow = tid + 128;
            #pragma unroll
            for (int i = 0; i < 16; ++i) {
                sBT[(4 * i + 0) * BPITCH + srow] = pf[i].x;
                sBT[(4 * i + 1) * BPITCH + srow] = pf[i].y;
                sBT[(4 * i + 2) * BPITCH + srow] = pf[i].z;
                sBT[(4 * i + 3) * BPITCH + srow] = pf[i].w;
            }
        }
        __syncthreads();

        // prefetch next chunk half 0 (hidden under GEMM)
        if (c + 1 < NCHUNK) {
            const float4* src = reinterpret_cast<const float4*>(
                inp + ((size_t)(((c + 1) * SC + tid) * BATCH + b)) * HID);
            #pragma unroll
            for (int i = 0; i < 16; ++i) pf[i] = src[i];
        }

        // ---- GEMM micro-tile: 4 rows x 8 cols per lane (4 f32x2 col-pairs) ----
        ull acc[4][4];
        #pragma unroll
        for (int r = 0; r < 4; ++r)
            #pragma unroll
            for (int j = 0; j < 4; ++j) acc[r][j] = 0ull;

        const float* aBase = sAT + rg * 4;
        const float* bBase = sBT + colbase;
        #pragma unroll 16
        for (int h = 0; h < HID; ++h) {
            const float4 av = *reinterpret_cast<const float4*>(aBase + h * 16);
            const ull a0 = pack_dup(av.x);
            const ull a1 = pack_dup(av.y);
            const ull a2 = pack_dup(av.z);
            const ull a3 = pack_dup(av.w);
            const float* bRow = bBase + h * BPITCH;
            #pragma unroll
            for (int j = 0; j < 4; ++j) {
                const ull bv = *reinterpret_cast<const ull*>(bRow + 16 * j);
                fma2(acc[0][j], a0, bv);
                fma2(acc[1][j], a1, bv);
                fma2(acc[2][j], a2, bv);
                fma2(acc[3][j], a3, bv);
            }
        }
        // store scores (STS.64, conflict-free with SSP=2052)
        float* dst = sS + c * SC + colbase;
        #pragma unroll
        for (int r = 0; r < 4; ++r) {
            float* drow = dst + (rg * 4 + r) * SSP;
            #pragma unroll
            for (int j = 0; j < 4; ++j)
                *reinterpret_cast<ull*>(drow + 16 * j) = acc[r][j];
        }
    }
    __syncthreads();

    // ---------------- register-resident epilogue: warp handles 4 rows ----------
    const float NEG_INF = __int_as_float(0xff800000);
    #pragma unroll
    for (int rr = 0; rr < 4; ++rr) {
        const int r = wid * 4 + rr;
        const float* row = sS + r * SSP;
        const size_t gbase = ((size_t)(b * S_T + (t0 + r))) * S_IN;

        // load full row into registers (64 regs) + sum
        float4 v[16];
        float s = 0.f;
        #pragma unroll
        for (int i = 0; i < 16; ++i) {
            v[i] = *reinterpret_cast<const float4*>(row + i * 128 + lane * 4);
            s += (v[i].x + v[i].y) + (v[i].z + v[i].w);
        }
        s = warp_sum(s);
        const float mean = s * (1.0f / 2048.0f);

        // y = |x - mean|, apply mask (-inf), track max (all in registers)
        float m = NEG_INF;
        #pragma unroll
        for (int i = 0; i < 16; ++i) {
            const unsigned int mk = *reinterpret_cast<const unsigned int*>(
                msk + gbase + i * 128 + lane * 4);
            v[i].x = fabsf(v[i].x - mean);
            v[i].y = fabsf(v[i].y - mean);
            v[i].z = fabsf(v[i].z - mean);
            v[i].w = fabsf(v[i].w - mean);
            if (mk & 0x000000FFu) v[i].x = NEG_INF;
            if (mk & 0x0000FF00u) v[i].y = NEG_INF;
            if (mk & 0x00FF0000u) v[i].z = NEG_INF;
            if (mk & 0xFF000000u) v[i].w = NEG_INF;
            m = fmaxf(m, fmaxf(fmaxf(v[i].x, v[i].y), fmaxf(v[i].z, v[i].w)));
        }
        m = warp_max(m);

        // e = exp(y - max); sum
        float l = 0.f;
        #pragma unroll
        for (int i = 0; i < 16; ++i) {
            v[i].x = __expf(v[i].x - m);
            v[i].y = __expf(v[i].y - m);
            v[i].z = __expf(v[i].z - m);
            v[i].w = __expf(v[i].w - m);
            l += (v[i].x + v[i].y) + (v[i].z + v[i].w);
        }
        l = warp_sum(l);
        const float inv = 1.0f / l;

        // write normalized probabilities straight to GMEM
        #pragma unroll
        for (int i = 0; i < 16; ++i) {
            v[i].x *= inv; v[i].y *= inv; v[i].z *= inv; v[i].w *= inv;
            *reinterpret_cast<float4*>(out + gbase + i * 128 + lane * 4) = v[i];
        }
    }
}

extern "C" void kernel_launch(void* const* d_in, const int* in_sizes, int n_in,
                              void* d_out, int out_size)
{
    const float*         inp  = (const float*)d_in[0];
    const float*         tgt  = (const float*)d_in[1];
    const unsigned char* msk  = (const unsigned char*)d_in[2];
    const float*         Wm   = (const float*)d_in[3];
    const float*         bias = (const float*)d_in[4];
    float*               out  = (float*)d_out;

    const int smem_bytes = SMEM_FLOATS * (int)sizeof(float); // 203008 B
    cudaFuncSetAttribute(attn_fused_kernel,
                         cudaFuncAttributeMaxDynamicSharedMemorySize, smem_bytes);

    dim3 grid(BATCH * (S_T / TM));  // 1024 CTAs
    dim3 block(THREADS);
    attn_fused_kernel<<<grid, block, smem_bytes>>>(inp, tgt, msk, Wm, bias, out);
}

// round 12
// speedup vs baseline: 1.6175x; 1.5558x over previous
#include <cuda_runtime.h>
#include <cstdint>

// Shapes (fixed by the problem)
#define S_IN   2048
#define S_T    2048
#define BATCH  8
#define HID    64

#define TM      16           // t-rows per CTA
#define THREADS 256          // 8 warps; warp w owns s-cols {j*64 + w*8 .. +7}, j=0..31
#define SSP     2056         // sS pitch (floats)
#define LPITCH  68           // sWT staging pitch
#define BP      68           // per-warp B staging pitch (conflict-free frag LDS)

// SMEM (floats): sS[16][SSP] | sP[16][64] | stage[8 warps][8][BP]
#define SS_FLOATS   (TM * SSP)
#define SP_OFF      SS_FLOATS
#define STAGE_OFF   (SP_OFF + TM * HID)
#define SMEM_FLOATS (STAGE_OFF + 8 * 8 * BP)

__device__ __forceinline__ float tf32_hi(float x) {
    uint32_t u;
    asm("cvt.rna.tf32.f32 %0, %1;" : "=r"(u) : "f"(x));
    return __uint_as_float(u);
}

// D = A(16x8,row) * B(8x8,col) + D, tf32 inputs, f32 accum
__device__ __forceinline__ void mma8(float c[4], const float a[4], float b0, float b1) {
    asm volatile(
        "mma.sync.aligned.m16n8k8.row.col.f32.tf32.tf32.f32 "
        "{%0,%1,%2,%3}, {%4,%5,%6,%7}, {%8,%9}, {%0,%1,%2,%3};"
        : "+f"(c[0]), "+f"(c[1]), "+f"(c[2]), "+f"(c[3])
        : "r"(__float_as_uint(a[0])), "r"(__float_as_uint(a[1])),
          "r"(__float_as_uint(a[2])), "r"(__float_as_uint(a[3])),
          "r"(__float_as_uint(b0)),  "r"(__float_as_uint(b1)));
}

__device__ __forceinline__ float warp_sum(float v) {
    v += __shfl_xor_sync(0xffffffffu, v, 16);
    v += __shfl_xor_sync(0xffffffffu, v, 8);
    v += __shfl_xor_sync(0xffffffffu, v, 4);
    v += __shfl_xor_sync(0xffffffffu, v, 2);
    v += __shfl_xor_sync(0xffffffffu, v, 1);
    return v;
}
__device__ __forceinline__ float warp_max(float v) {
    v = fmaxf(v, __shfl_xor_sync(0xffffffffu, v, 16));
    v = fmaxf(v, __shfl_xor_sync(0xffffffffu, v, 8));
    v = fmaxf(v, __shfl_xor_sync(0xffffffffu, v, 4));
    v = fmaxf(v, __shfl_xor_sync(0xffffffffu, v, 2));
    v = fmaxf(v, __shfl_xor_sync(0xffffffffu, v, 1));
    return v;
}

__global__ void __launch_bounds__(THREADS, 1)
attn_mma_kernel(const float* __restrict__ inp,        // (S_IN, B, H)
                const float* __restrict__ tgt,        // (S_T, B, H)
                const unsigned char* __restrict__ msk,// (B, S_T, S_IN) bool
                const float* __restrict__ Wm,         // (H, H)  W[o][h]
                const float* __restrict__ bias,       // (H)
                float* __restrict__ out)              // (B, S_T, S_IN)
{
    extern __shared__ float sm[];
    float* sS = sm;                     // scores, pitch SSP
    float* sP = sm + SP_OFF;            // P = tgt_tile @ W^T + b, [16][64]
    float* sStage = sm + STAGE_OFF;     // per-warp B slots [8][8][BP]

    const int tid  = threadIdx.x;
    const int w    = tid >> 5;
    const int l    = tid & 31;
    const int b    = blockIdx.x >> 7;
    const int t0   = (blockIdx.x & 127) << 4;

    // ---------------- linear stage: P = tgt_tile @ W^T + bias -----------------
    {
        float* sWT = sS;                 // [64][LPITCH]
        float* sTg = sS + HID * LPITCH;  // [16][64]
        const int o  = tid >> 2;
        const int hq = (tid & 3) * 16;
        #pragma unroll
        for (int k = 0; k < 4; ++k) {
            float4 wv = *reinterpret_cast<const float4*>(Wm + o * HID + hq + 4 * k);
            sWT[(hq + 4 * k + 0) * LPITCH + o] = wv.x;
            sWT[(hq + 4 * k + 1) * LPITCH + o] = wv.y;
            sWT[(hq + 4 * k + 2) * LPITCH + o] = wv.z;
            sWT[(hq + 4 * k + 3) * LPITCH + o] = wv.w;
        }
        const int r  = tid >> 4;
        const int hh = (tid & 15) * 4;
        *reinterpret_cast<float4*>(sTg + r * HID + hh) =
            *reinterpret_cast<const float4*>(tgt + ((size_t)((t0 + r) * BATCH + b)) * HID + hh);
        __syncthreads();

        const int o0 = (tid & 15) * 4;
        float4 acc = *reinterpret_cast<const float4*>(bias + o0);
        #pragma unroll
        for (int h = 0; h < HID; ++h) {
            const float  tv = sTg[r * HID + h];
            const float4 wv = *reinterpret_cast<const float4*>(sWT + h * LPITCH + o0);
            acc.x += tv * wv.x;
            acc.y += tv * wv.y;
            acc.z += tv * wv.z;
            acc.w += tv * wv.w;
        }
        *reinterpret_cast<float4*>(sP + r * HID + o0) = acc;
        __syncthreads();   // P visible; sS region free for scores
    }

    // ---------------- preload A fragments (hi/lo tf32 split) ------------------
    // a0=(r,l%4) a1=(r+8,l%4) a2=(r,l%4+4) a3=(r+8,l%4+4), r = l/4, k-block kk
    float ah[8][4], al[8][4];
    {
        const float* p0 = sP + (l >> 2) * HID;
        const float* p1 = p0 + 8 * HID;
        #pragma unroll
        for (int kk = 0; kk < 8; ++kk) {
            const int k0 = kk * 8 + (l & 3);
            const float a0 = p0[k0], a1 = p1[k0], a2 = p0[k0 + 4], a3 = p1[k0 + 4];
            ah[kk][0] = tf32_hi(a0); al[kk][0] = a0 - ah[kk][0];
            ah[kk][1] = tf32_hi(a1); al[kk][1] = a1 - ah[kk][1];
            ah[kk][2] = tf32_hi(a2); al[kk][2] = a2 - ah[kk][2];
            ah[kk][3] = tf32_hi(a3); al[kk][3] = a3 - ah[kk][3];
        }
    }

    // ---------------- score GEMM: 32 tiles of 8 s-cols per warp ---------------
    float* slot = sStage + w * (8 * BP);
    const int rr4 = l >> 2;              // staging/frag row 0..7
    const int hq4 = (l & 3) * 16;        // 16-float h range owned for LDG/STS

    float4 pf[4];
    {   // prefetch tile 0: s = w*8 + row
        const float4* src = reinterpret_cast<const float4*>(
            inp + ((size_t)((w * 8 + rr4) * BATCH + b)) * HID + hq4);
        #pragma unroll
        for (int q = 0; q < 4; ++q) pf[q] = src[q];
    }

    #pragma unroll 4
    for (int j = 0; j < 32; ++j) {
        __syncwarp();                    // prior frag LDS done before overwrite
        #pragma unroll
        for (int q = 0; q < 4; ++q)
            *reinterpret_cast<float4*>(slot + rr4 * BP + hq4 + 4 * q) = pf[q];
        __syncwarp();
        if (j + 1 < 32) {               // prefetch next tile under the MMAs
            const int s = (j + 1) * 64 + w * 8 + rr4;
            const float4* src = reinterpret_cast<const float4*>(
                inp + ((size_t)(s * BATCH + b)) * HID + hq4);
            #pragma unroll
            for (int q = 0; q < 4; ++q) pf[q] = src[q];
        }

        float c[4] = {0.f, 0.f, 0.f, 0.f};
        const float* bp = slot + rr4 * BP + (l & 3);
        #pragma unroll
        for (int kk = 0; kk < 8; ++kk) {
            const float b0 = bp[kk * 8];
            const float b1 = bp[kk * 8 + 4];
            const float b0h = tf32_hi(b0), b0l = b0 - b0h;
            const float b1h = tf32_hi(b1), b1l = b1 - b1h;
            mma8(c, ah[kk], b0h, b1h);   // hi*hi
            mma8(c, al[kk], b0h, b1h);   // lo*hi
            mma8(c, ah[kk], b0l, b1l);   // hi*lo
        }
        // c0,c1 -> row l/4, cols s0+2*(l%4)+{0,1}; c2,c3 -> row l/4+8
        float* dst = sS + rr4 * SSP + j * 64 + w * 8 + 2 * (l & 3);
        *reinterpret_cast<float2*>(dst)            = make_float2(c[0], c[1]);
        *reinterpret_cast<float2*>(dst + 8 * SSP)  = make_float2(c[2], c[3]);
    }
    __syncthreads();

    // ---------------- register-resident epilogue: warp w -> rows 2w, 2w+1 -----
    const float NEG_INF = __int_as_float(0xff800000);
    #pragma unroll
    for (int rr = 0; rr < 2; ++rr) {
        const int r = w * 2 + rr;
        const float* row = sS + r * SSP;
        const size_t gbase = ((size_t)(b * S_T + (t0 + r))) * S_IN;

        float4 v[16];
        float s = 0.f;
        #pragma unroll
        for (int i = 0; i < 16; ++i) {
            v[i] = *reinterpret_cast<const float4*>(row + i * 128 + l * 4);
            s += (v[i].x + v[i].y) + (v[i].z + v[i].w);
        }
        s = warp_sum(s);
        const float mean = s * (1.0f / 2048.0f);

        float m = NEG_INF;
        #pragma unroll
        for (int i = 0; i < 16; ++i) {
            const unsigned int mk = *reinterpret_cast<const unsigned int*>(
                msk + gbase + i * 128 + l * 4);
            v[i].x = fabsf(v[i].x - mean);
            v[i].y = fabsf(v[i].y - mean);
            v[i].z = fabsf(v[i].z - mean);
            v[i].w = fabsf(v[i].w - mean);
            if (mk & 0x000000FFu) v[i].x = NEG_INF;
            if (mk & 0x0000FF00u) v[i].y = NEG_INF;
            if (mk & 0x00FF0000u) v[i].z = NEG_INF;
            if (mk & 0xFF000000u) v[i].w = NEG_INF;
            m = fmaxf(m, fmaxf(fmaxf(v[i].x, v[i].y), fmaxf(v[i].z, v[i].w)));
        }
        m = warp_max(m);

        float lsum = 0.f;
        #pragma unroll
        for (int i = 0; i < 16; ++i) {
            v[i].x = __expf(v[i].x - m);
            v[i].y = __expf(v[i].y - m);
            v[i].z = __expf(v[i].z - m);
            v[i].w = __expf(v[i].w - m);
            lsum += (v[i].x + v[i].y) + (v[i].z + v[i].w);
        }
        lsum = warp_sum(lsum);
        const float inv = 1.0f / lsum;

        #pragma unroll
        for (int i = 0; i < 16; ++i) {
            v[i].x *= inv; v[i].y *= inv; v[i].z *= inv; v[i].w *= inv;
            *reinterpret_cast<float4*>(out + gbase + i * 128 + l * 4) = v[i];
        }
    }
}

extern "C" void kernel_launch(void* const* d_in, const int* in_sizes, int n_in,
                              void* d_out, int out_size)
{
    const float*         inp  = (const float*)d_in[0];
    const float*         tgt  = (const float*)d_in[1];
    const unsigned char* msk  = (const unsigned char*)d_in[2];
    const float*         Wm   = (const float*)d_in[3];
    const float*         bias = (const float*)d_in[4];
    float*               out  = (float*)d_out;

    const int smem_bytes = SMEM_FLOATS * (int)sizeof(float); // ~153 KB
    cudaFuncSetAttribute(attn_mma_kernel,
                         cudaFuncAttributeMaxDynamicSharedMemorySize, smem_bytes);

    dim3 grid(BATCH * (S_T / TM));  // 1024 CTAs
    dim3 block(THREADS);
    attn_mma_kernel<<<grid, block, smem_bytes>>>(inp, tgt, msk, Wm, bias, out);
}